// round 17
// baseline (speedup 1.0000x reference)
#include <cuda_runtime.h>
#include <cstdint>

#define BSZ 4
#define LM  256
#define LE  512
#define HD  512
#define VOC 32000

#define STAGES 3
#define TILEF  2304      // floats per A or B stage buffer (64*36 or 32*72)
#define GSMEM  (STAGES * 2 * TILEF * 4)   // 55296 B dynamic smem per block

#define NGEMM 256u       // GEMM-role blocks
#define NZERO 148u       // zero-role blocks
#define NALL  (NGEMM + NZERO)             // 404 total, co-resident (cap 592)
#define N4TOT 8192000L                    // BSZ*LM*VOC/4 float4s of output

// Scratch (device globals; no allocation allowed in kernel_launch)
__device__ float g_G[HD * HD];               // Wm @ We^T * scale    (1 MB)
__device__ float g_T[BSZ * LM * HD];         // M @ G                (2 MB)
__device__ float g_log[4][BSZ * LM * LE];    // logits K-split partials (8 MB)
__device__ unsigned g_barc[5];               // barrier counters (zero-init)

// ---------------------------------------------------------------------------
// Software barrier among a subset of co-resident blocks.
// ---------------------------------------------------------------------------
__device__ __forceinline__ void gbar(int k, unsigned target)
{
    __syncthreads();
    if (threadIdx.x == 0) {
        __threadfence();
        atomicAdd(&g_barc[k], 1u);
        while (*(volatile unsigned*)&g_barc[k] < target) __nanosleep(64);
        __threadfence();
    }
    __syncthreads();
}

// ---------------------------------------------------------------------------
// tf32 tensor-core GEMM core: 64x64 tile, 256 threads, BK=32, 3-stage
// cp.async pipeline, mma.sync.m16n8k8.tf32.
// TB=true:  C[m,n] (+)= alpha * sum_k A[m,k] * B[n,k]   (NT)
// TB=false: C[m,n] (+)= alpha * sum_k A[m,k] * B[k,n]   (NN)
// ATOMIC=true: accumulate with atomicAdd (K-split partial sums).
// ---------------------------------------------------------------------------
__device__ __forceinline__ void cp16(void* dst, const void* src)
{
    uint32_t d = (uint32_t)__cvta_generic_to_shared(dst);
    asm volatile("cp.async.cg.shared.global [%0], [%1], 16;\n"
                 :: "r"(d), "l"(src));
}
__device__ __forceinline__ void cp_commit()
{
    asm volatile("cp.async.commit_group;\n" ::: "memory");
}
__device__ __forceinline__ void cp_wait0()
{
    asm volatile("cp.async.wait_group 0;\n" ::: "memory");
}
__device__ __forceinline__ void cp_wait1()
{
    asm volatile("cp.async.wait_group 1;\n" ::: "memory");
}
__device__ __forceinline__ void mma_tf32(float* d, const uint32_t* a,
                                         const uint32_t* b)
{
    asm volatile(
        "mma.sync.aligned.m16n8k8.row.col.f32.tf32.tf32.f32 "
        "{%0,%1,%2,%3}, {%4,%5,%6,%7}, {%8,%9}, {%0,%1,%2,%3};\n"
        : "+f"(d[0]), "+f"(d[1]), "+f"(d[2]), "+f"(d[3])
        : "r"(a[0]), "r"(a[1]), "r"(a[2]), "r"(a[3]),
          "r"(b[0]), "r"(b[1]));
}

#define PA 36   // smem pitch, K-major tiles (banks 4*gid+tig: conflict-free)
#define PB 72   // smem pitch, NN B tile     (banks 8*tig+gid: conflict-free)

template <bool TB, bool ATOMIC>
__device__ __forceinline__ void gemm_core(
    const float* __restrict__ A, const float* __restrict__ B,
    float* __restrict__ C, int lda, int ldb, int ldc,
    int m0, int n0, int kOff, int kLen, float alpha, float* smem)
{
    float (*As)[TILEF] = reinterpret_cast<float(*)[TILEF]>(smem);
    float (*Bs)[TILEF] = reinterpret_cast<float(*)[TILEF]>(smem
                                                           + STAGES * TILEF);

    const int tid  = threadIdx.x;
    const int lane = tid & 31, w = tid >> 5;
    const int gid = lane >> 2, tig = lane & 3;
    const int wm = (w & 3) * 16, wn = (w >> 2) * 32;

    const int NK = kLen / 32;

    auto loadA = [&](int st, int kt) {
        int k0 = kOff + kt * 32;
#pragma unroll
        for (int i = 0; i < 2; i++) {
            int id = tid + i * 256;
            int row = id >> 3, cc = id & 7;
            cp16(&As[st][row * PA + cc * 4],
                 A + (long)(m0 + row) * lda + k0 + cc * 4);
        }
    };
    auto loadB = [&](int st, int kt) {
        int k0 = kOff + kt * 32;
        if (TB) {
#pragma unroll
            for (int i = 0; i < 2; i++) {
                int id = tid + i * 256;
                int row = id >> 3, cc = id & 7;
                cp16(&Bs[st][row * PA + cc * 4],
                     B + (long)(n0 + row) * ldb + k0 + cc * 4);
            }
        } else {
#pragma unroll
            for (int i = 0; i < 2; i++) {
                int id = tid + i * 256;
                int row = id >> 4, cc = id & 15;
                cp16(&Bs[st][row * PB + cc * 4],
                     B + (long)(k0 + row) * ldb + n0 + cc * 4);
            }
        }
    };

    float acc[4][4] = {};

    loadA(0, 0); loadB(0, 0); cp_commit();
    if (NK > 1) { loadA(1, 1); loadB(1, 1); cp_commit(); }

    int buf = 0, ls = 2;
    for (int kt = 0; kt < NK; kt++) {
        if (kt < NK - 1) cp_wait1(); else cp_wait0();
        __syncthreads();
        if (kt + 2 < NK) {
            loadA(ls, kt + 2);
            loadB(ls, kt + 2);
            cp_commit();
            ls = (ls == STAGES - 1) ? 0 : ls + 1;
        }
#pragma unroll
        for (int ks = 0; ks < 4; ks++) {
            const int kk = ks * 8;
            uint32_t a[4];
            {
                int rb = wm + gid;
                a[0] = __float_as_uint(As[buf][(rb)     * PA + kk + tig]);
                a[1] = __float_as_uint(As[buf][(rb + 8) * PA + kk + tig]);
                a[2] = __float_as_uint(As[buf][(rb)     * PA + kk + tig + 4]);
                a[3] = __float_as_uint(As[buf][(rb + 8) * PA + kk + tig + 4]);
            }
            uint32_t b[4][2];
#pragma unroll
            for (int nj = 0; nj < 4; nj++) {
                int cb = wn + nj * 8 + gid;
                if (TB) {
                    b[nj][0] = __float_as_uint(Bs[buf][cb * PA + kk + tig]);
                    b[nj][1] = __float_as_uint(Bs[buf][cb * PA + kk + tig + 4]);
                } else {
                    b[nj][0] = __float_as_uint(Bs[buf][(kk + tig)     * PB + cb]);
                    b[nj][1] = __float_as_uint(Bs[buf][(kk + tig + 4) * PB + cb]);
                }
            }
#pragma unroll
            for (int nj = 0; nj < 4; nj++)
                mma_tf32(acc[nj], a, b[nj]);
        }
        buf = (buf == STAGES - 1) ? 0 : buf + 1;
    }

    cp_wait0();          // drain so no cp.async groups leak into next phase
    __syncthreads();

#pragma unroll
    for (int nj = 0; nj < 4; nj++) {
        int r0 = m0 + wm + gid;
        int c0 = n0 + wn + nj * 8 + 2 * tig;
        if (ATOMIC) {
            atomicAdd(&C[(long)r0 * ldc + c0],           acc[nj][0] * alpha);
            atomicAdd(&C[(long)r0 * ldc + c0 + 1],       acc[nj][1] * alpha);
            atomicAdd(&C[(long)(r0 + 8) * ldc + c0],     acc[nj][2] * alpha);
            atomicAdd(&C[(long)(r0 + 8) * ldc + c0 + 1], acc[nj][3] * alpha);
        } else {
            C[(long)r0 * ldc + c0]           = acc[nj][0] * alpha;
            C[(long)r0 * ldc + c0 + 1]       = acc[nj][1] * alpha;
            C[(long)(r0 + 8) * ldc + c0]     = acc[nj][2] * alpha;
            C[(long)(r0 + 8) * ldc + c0 + 1] = acc[nj][3] * alpha;
        }
    }
}

// ---------------------------------------------------------------------------
// Block reduction for 256 threads (8 warps).
// ---------------------------------------------------------------------------
__device__ __forceinline__ float bred256(float v, bool mx, float* red8,
                                         int lane, int w)
{
#pragma unroll
    for (int o = 16; o > 0; o >>= 1) {
        float u = __shfl_xor_sync(0xffffffffu, v, o);
        v = mx ? fmaxf(v, u) : v + u;
    }
    if (lane == 0) red8[w] = v;
    __syncthreads();
    float x = red8[lane & 7];
#pragma unroll
    for (int o = 4; o > 0; o >>= 1) {
        float u = __shfl_xor_sync(0xffffffffu, x, o);
        x = mx ? fmaxf(x, u) : x + u;
    }
    __syncthreads();
    return x;
}

// ---------------------------------------------------------------------------
// Mega kernel, grid = 404 co-resident blocks, ONE launch:
//   blocks [0,256):  GEMM chain (zero accum -> G -> T -> logit partials),
//                    sub-barriers among the 256 GEMM blocks only
//   blocks [256,404): stream 131 MB of zeros over out CONCURRENTLY
//   all 404:         join (counter target 404), then patch rows with
//                    lambda + dual softmax + 512 global atomicAdd per row
// Counters self-reset via a final exit arrival (nobody waits on it).
// ---------------------------------------------------------------------------
__global__ __launch_bounds__(256) void k_mega(
    const float* __restrict__ Wm, const float* __restrict__ We,
    const float* __restrict__ Mi, const float* __restrict__ E,
    float scale, const int* __restrict__ idx,
    const float* __restrict__ bq, const float* __restrict__ bc,
    const float* __restrict__ D, const float* __restrict__ Cq,
    const float* __restrict__ Cc, const float* __restrict__ Wl,
    const float* __restrict__ bl, float* __restrict__ out)
{
    extern __shared__ float smem[];
    __shared__ float red8[8];
    const int bid = blockIdx.x;
    const int t = threadIdx.x, lane = t & 31, w = t >> 5;

    if (bid < (int)NGEMM) {
        // ---- GEMM role ----------------------------------------------------
        // phase 0: zero G + T accumulators (3 MB)
        {
            float4* a = (float4*)g_G;
            float4* b4 = (float4*)g_T;
            const long na4 = HD * HD / 4;
            const long nb4 = (long)BSZ * LM * HD / 4;
            for (long i = bid * 256 + t; i < na4; i += 256 * NGEMM)
                a[i] = make_float4(0.f, 0.f, 0.f, 0.f);
            for (long i = bid * 256 + t; i < nb4; i += 256 * NGEMM)
                b4[i] = make_float4(0.f, 0.f, 0.f, 0.f);
        }
        gbar(0, NGEMM);

        // phase 1: G = Wm @ We^T * scale (256 tasks, K-split x4, atomic)
        {
            int nx = bid & 7, my = (bid >> 3) & 7, h = bid >> 6;
            gemm_core<true, true>(Wm, We, g_G, HD, HD, HD,
                                  my * 64, nx * 64, h * 128, 128, scale, smem);
        }
        gbar(1, NGEMM);

        // phase 2: T = M_flat @ G (256 tasks, K-split x2, atomic)
        {
            int nx = bid & 7, my = (bid >> 3) & 15, h = bid >> 7;
            gemm_core<false, true>(Mi, g_G, g_T, HD, HD, HD,
                                   my * 64, nx * 64, h * 256, 256, 1.f, smem);
        }
        gbar(2, NGEMM);

        // phase 3: logit partials (512 tasks, 2 per block, non-atomic)
#pragma unroll
        for (int rep = 0; rep < 2; rep++) {
            int tk = bid + rep * NGEMM;
            int nx = tk & 7, my = (tk >> 3) & 3, z = tk >> 5;
            int b = z >> 2, h = z & 3;
            const float* A = g_T + (long)b * LM * HD;
            const float* B = E + (long)b * LE * HD;
            float* C = g_log[h] + (long)b * LM * LE;
            gemm_core<true, false>(A, B, C, HD, HD, LE,
                                   my * 64, nx * 64, h * 128, 128, 1.f, smem);
        }
    } else {
        // ---- zero role: stream 131 MB of zeros over out -------------------
        int zb = bid - (int)NGEMM;           // 0..147
        float4* o4 = (float4*)out;
        float4 z = make_float4(0.f, 0.f, 0.f, 0.f);
        for (long i = (long)zb * 256 + t; i < N4TOT; i += 256L * NZERO)
            __stcs(o4 + i, z);
    }

    // ---- join: logits AND zeros complete ----------------------------------
    gbar(3, NALL);

    // ---- patch: rows bid, bid+404, ... (<= 3 rows per block) --------------
    for (int r = bid; r < BSZ * LM; r += (int)NALL) {
        const int b = r >> 8;

        const float* dr  = D  + (long)r * HD;
        const float* cqr = Cq + (long)r * HD;
        const float* ccr = Cc + (long)r * HD;
        float s = 0.f;
#pragma unroll
        for (int i = 0; i < 2; i++) {
            int j = t + i * 256;
            s += dr[j] * Wl[j] + cqr[j] * Wl[HD + j] + ccr[j] * Wl[2 * HD + j];
        }
        s = bred256(s, false, red8, lane, w);
        float lam = 1.f / (1.f + __expf(-(s + bl[0])));

        float vq[2], vc[2];
#pragma unroll
        for (int i = 0; i < 2; i++) {
            int e = t + i * 256;
            long rl = (long)r * LE + e;
            float l = g_log[0][rl] + g_log[1][rl] + g_log[2][rl] + g_log[3][rl];
            vq[i] = l + bq[b * LE + e];
            vc[i] = l + bc[b * LE + e];
        }

        float mq = bred256(fmaxf(vq[0], vq[1]), true, red8, lane, w);
        float mc = bred256(fmaxf(vc[0], vc[1]), true, red8, lane, w);
        float eq[2], ec[2];
        eq[0] = __expf(vq[0] - mq); eq[1] = __expf(vq[1] - mq);
        ec[0] = __expf(vc[0] - mc); ec[1] = __expf(vc[1] - mc);
        float sq = bred256(eq[0] + eq[1], false, red8, lane, w);
        float sc = bred256(ec[0] + ec[1], false, red8, lane, w);

        float iq = lam / sq, ic = (1.f - lam) / sc;
        float* orow = out + (long)r * VOC;
#pragma unroll
        for (int i = 0; i < 2; i++) {
            int e = t + i * 256;
            atomicAdd(orow + idx[b * LE + e], eq[i] * iq + ec[i] * ic);
        }
        __syncthreads();
    }

    // ---- exit arrival: 404th block resets counters (nobody waits here) ----
    __syncthreads();
    if (t == 0) {
        __threadfence();
        unsigned old = atomicAdd(&g_barc[4], 1u);
        if (old == NALL - 1u) {
            g_barc[0] = 0; g_barc[1] = 0; g_barc[2] = 0;
            g_barc[3] = 0; g_barc[4] = 0;
        }
    }
}

// ---------------------------------------------------------------------------
extern "C" void kernel_launch(void* const* d_in, const int* in_sizes, int n_in,
                              void* d_out, int out_size)
{
    const int*   inputs = (const int*)  d_in[0];
    const float* D      = (const float*)d_in[1];
    const float* Cq     = (const float*)d_in[2];
    const float* Cc     = (const float*)d_in[3];
    const float* Mi     = (const float*)d_in[4];
    const float* E      = (const float*)d_in[5];
    const float* bq     = (const float*)d_in[6];
    const float* bc     = (const float*)d_in[7];
    const float* Wl     = (const float*)d_in[8];
    const float* bl     = (const float*)d_in[9];
    const float* We     = (const float*)d_in[10];
    const float* Wm     = (const float*)d_in[11];
    float* out = (float*)d_out;

    static bool init = false;
    if (!init) {
        cudaFuncSetAttribute(k_mega,
                             cudaFuncAttributeMaxDynamicSharedMemorySize,
                             GSMEM);
        init = true;
    }

    const float scale = 0.044194173824159216f;  // 512^-0.5

    // one launch: GEMM chain + concurrent 131 MB zero stream + sparse patch
    k_mega<<<NALL, 256, GSMEM>>>(Wm, We, Mi, E, scale,
                                 inputs, bq, bc, D, Cq, Cc, Wl, bl, out);
}